// round 5
// baseline (speedup 1.0000x reference)
#include <cuda_runtime.h>
#include <math.h>

#define TPB 256
#define S_REAL 35
#define S_PAD 40
#define DM 64
#define STATE 24
#define MEMN 10

// smem layout (float offsets)
#define WT_F   0        // 8192 floats (32KB) weight tile, k4-major float4
#define HTS_F  8192     // 5120 floats (40x128) : FF hidden tile / attn-out / head scratch
#define QKV_F  13312    // 7680 floats (40x192)
#define XS_F   20992    // 2560 floats (40x64)
#define YS_F   23552    // 2560 floats (40x64)
#define RED_F  26112    // 8 floats
#define SMEM_FLOATS 26120
#define SMEM_BYTES (SMEM_FLOATS * 4)

static __device__ float g_base[STATE * DM];

__device__ __forceinline__ unsigned long long ffma2(double a, double b, unsigned long long c) {
    unsigned long long r;
    asm("fma.rn.f32x2 %0, %1, %2, %3;"
        : "=l"(r)
        : "l"(__double_as_longlong(a)), "l"(__double_as_longlong(b)), "l"(c));
    return r;
}

__device__ __forceinline__ float unpack_sum(unsigned long long a) {
    float lo = __uint_as_float((unsigned)(a & 0xFFFFFFFFull));
    float hi = __uint_as_float((unsigned)(a >> 32));
    return lo + hi;
}

__device__ __forceinline__ float gelu_f(float x) {
    return 0.5f * x * (1.0f + erff(x * 0.7071067811865475f));
}

// Load weight tile into smem as wt[k4][n] (float4 per entry), so that in the GEMM
// inner loop lanes read consecutive 16B (conflict-free) while x rows broadcast.
template<int K4C>
__device__ __forceinline__ void load_wt(float4* wt, const float4* Wf4, int nrows,
                                        int rowStrideF4, int k4off, int tid) {
    int tot = nrows * K4C;
    for (int idx = tid; idx < tot; idx += TPB) {
        int n = idx / K4C;
        int k4 = idx - n * K4C;
        wt[k4 * nrows + n] = Wf4[n * rowStrideF4 + k4off + k4];
    }
}

// out[s][ooff+n] (+)= act( bias[n] + sum_k x[s][k] * W[n][k] )
// x: smem [40][K4*4] floats (row-contiguous). wt: smem [K4][NT] float4.
// thread (ty,tx): rows s = ty*5..ty*5+4, cols n = tx + c*32 (c < NC).
template<int NC, int K4, int NT, bool GELUA, bool ACC>
__device__ __forceinline__ void gemm_tile(const float* xsrc, const float* wtf,
                                          float* out, int ostride, int ooff,
                                          const float* bias, int tx, int ty) {
    const double2* x2 = reinterpret_cast<const double2*>(xsrc);
    const double2* wt = reinterpret_cast<const double2*>(wtf);
    unsigned long long acc[5][NC];
#pragma unroll
    for (int r = 0; r < 5; r++)
#pragma unroll
        for (int c = 0; c < NC; c++) acc[r][c] = 0ull;

    const int s0 = ty * 5;
#pragma unroll
    for (int k4 = 0; k4 < K4; k4++) {
        double2 xr[5];
#pragma unroll
        for (int r = 0; r < 5; r++) xr[r] = x2[(s0 + r) * K4 + k4];  // warp broadcast
#pragma unroll
        for (int c = 0; c < NC; c++) {
            double2 w = wt[k4 * NT + tx + c * 32];  // lanes consecutive 16B
#pragma unroll
            for (int r = 0; r < 5; r++) {
                acc[r][c] = ffma2(xr[r].x, w.x, acc[r][c]);
                acc[r][c] = ffma2(xr[r].y, w.y, acc[r][c]);
            }
        }
    }
#pragma unroll
    for (int r = 0; r < 5; r++) {
#pragma unroll
        for (int c = 0; c < NC; c++) {
            int n = tx + c * 32;
            float v = unpack_sum(acc[r][c]);
            if (bias) v += bias[n];
            if (GELUA) v = gelu_f(v);
            int oi = (s0 + r) * ostride + ooff + n;
            if (ACC) out[oi] += v; else out[oi] = v;
        }
    }
}

__device__ __forceinline__ void attention(const float* qkvs, float* ao, int tid) {
    const float scale = 0.35355339059327373f;  // 1/sqrt(8)
    for (int pair = tid; pair < 8 * S_REAL; pair += TPB) {
        int i = pair % S_REAL;
        int h = pair / S_REAL;
        const float* qp = qkvs + i * 192 + h * 8;
        float q[8];
#pragma unroll
        for (int d = 0; d < 8; d++) q[d] = qp[d];
        float sc[S_REAL];
        float mx = -1e30f;
#pragma unroll
        for (int j = 0; j < S_REAL; j++) {
            const float* kp = qkvs + j * 192 + 64 + h * 8;
            float a = 0.f;
#pragma unroll
            for (int d = 0; d < 8; d++) a += q[d] * kp[d];
            a *= scale;
            sc[j] = a;
            mx = fmaxf(mx, a);
        }
        float sum = 0.f;
#pragma unroll
        for (int j = 0; j < S_REAL; j++) { float e = __expf(sc[j] - mx); sc[j] = e; sum += e; }
        float inv = 1.f / sum;
#pragma unroll
        for (int d = 0; d < 8; d++) {
            float o = 0.f;
#pragma unroll
            for (int j = 0; j < S_REAL; j++) o += sc[j] * qkvs[j * 192 + 128 + h * 8 + d];
            ao[i * 64 + h * 8 + d] = o * inv;
        }
    }
}

__device__ __forceinline__ void layernorm(const float* src, float* dst,
                                          const float* g, const float* b, int tid) {
    int w = tid >> 5, lane = tid & 31;
    float g0 = g[lane], g1 = g[lane + 32], b0 = b[lane], b1 = b[lane + 32];
    for (int row = w; row < S_REAL; row += 8) {
        float v0 = src[row * 64 + lane], v1 = src[row * 64 + lane + 32];
        float s = v0 + v1, q = v0 * v0 + v1 * v1;
#pragma unroll
        for (int off = 16; off; off >>= 1) {
            s += __shfl_xor_sync(0xffffffffu, s, off);
            q += __shfl_xor_sync(0xffffffffu, q, off);
        }
        float m = s * (1.f / 64.f);
        float var = q * (1.f / 64.f) - m * m;
        float rs = rsqrtf(var + 1e-5f);
        dst[row * 64 + lane]      = (v0 - m) * rs * g0 + b0;
        dst[row * 64 + lane + 32] = (v1 - m) * rs * g1 + b1;
    }
}

// batch-independent: mean token embedding + positional + (trait_b + intent_b)
__global__ void base_kernel(const int* __restrict__ toks, const float* __restrict__ temb,
                            const float* __restrict__ demb, const float* __restrict__ trait_b,
                            const float* __restrict__ intent_b) {
    int i = blockIdx.x;
    int d = threadIdx.x;
    float s = 0.f;
#pragma unroll
    for (int t = 0; t < 8; t++) s += temb[(size_t)toks[i * 8 + t] * DM + d];
    g_base[i * DM + d] = s * 0.125f + demb[i * DM + d] + trait_b[d] + intent_b[d];
}

__global__ void __launch_bounds__(TPB, 2)
fused_kernel(const float* __restrict__ traits, const float* __restrict__ rel,
             const float* __restrict__ memc, const float* __restrict__ trait_W,
             const float* __restrict__ intent_W, const float* __restrict__ cls,
             const float* __restrict__ Wqkv, const float* __restrict__ bqkv,
             const float* __restrict__ Wo, const float* __restrict__ bo,
             const float* __restrict__ ln1g, const float* __restrict__ ln1b,
             const float* __restrict__ W1, const float* __restrict__ b1,
             const float* __restrict__ W2, const float* __restrict__ b2,
             const float* __restrict__ ln2g, const float* __restrict__ ln2b,
             const float* __restrict__ outW, const float* __restrict__ outb,
             const float* __restrict__ outlng, const float* __restrict__ outlnb,
             float* __restrict__ out_sit, float* __restrict__ out_seq,
             float* __restrict__ out_mem) {
    extern __shared__ float smem[];
    float* wtf  = smem + WT_F;
    float4* wt4 = reinterpret_cast<float4*>(wtf);
    float* hts  = smem + HTS_F;
    float* qkvs = smem + QKV_F;
    float* xs   = smem + XS_F;
    float* ys   = smem + YS_F;
    float* red  = smem + RED_F;

    const int tid = threadIdx.x;
    const int tx = tid & 31, ty = tid >> 5;
    const int b = blockIdx.x;

    // ---- build x[40][64] (rows >= 35 zero) ----
    for (int idx = tid; idx < S_PAD * DM; idx += TPB) {
        int s = idx >> 6, d = idx & 63;
        float v = 0.f;
        if (s == 0) {
            v = cls[d];
        } else if (s <= STATE) {
            int i = s - 1;
            float t0 = traits[(b * STATE + i) * 2];
            float t1 = traits[(b * STATE + i) * 2 + 1];
            v = g_base[i * DM + d] + t0 * trait_W[d * 2] + t1 * trait_W[d * 2 + 1]
                + rel[b * STATE + i] * intent_W[d];
        } else if (s < S_REAL) {
            v = memc[((size_t)b * MEMN + (s - 25)) * DM + d];
        }
        xs[idx] = v;
    }
    __syncthreads();

    for (int l = 0; l < 3; l++) {
        const float* Wq = Wqkv + l * 192 * 64;
        // ---- QKV (two 96-wide passes) ----
#pragma unroll
        for (int p = 0; p < 2; p++) {
            load_wt<16>(wt4, (const float4*)(Wq + p * 96 * 64), 96, 16, 0, tid);
            __syncthreads();
            gemm_tile<3, 16, 96, false, false>(xs, wtf, qkvs, 192, p * 96,
                                               bqkv + l * 192 + p * 96, tx, ty);
            __syncthreads();
        }
        // ---- attention -> ao (in hts) ----
        attention(qkvs, hts, tid);
        __syncthreads();
        // ---- y = x + ao @ Wo^T + bo ; x = LN1(y) ----
        load_wt<16>(wt4, (const float4*)(Wo + l * 64 * 64), 64, 16, 0, tid);
        for (int idx = tid; idx < S_PAD * DM; idx += TPB) ys[idx] = xs[idx];
        __syncthreads();
        gemm_tile<2, 16, 64, false, true>(hts, wtf, ys, 64, 0, bo + l * 64, tx, ty);
        __syncthreads();
        layernorm(ys, xs, ln1g + l * 64, ln1b + l * 64, tid);
        __syncthreads();
        // ---- FF: y = x + gelu(x@W1^T+b1)@W2^T+b2 ; x = LN2(y) ----
        for (int idx = tid; idx < S_PAD * DM; idx += TPB) ys[idx] = xs[idx];
        for (int jt = 0; jt < 4; jt++) {
            load_wt<16>(wt4, (const float4*)(W1 + (l * 512 + jt * 128) * 64), 128, 16, 0, tid);
            __syncthreads();
            gemm_tile<4, 16, 128, true, false>(xs, wtf, hts, 128, 0,
                                               b1 + l * 512 + jt * 128, tx, ty);
            __syncthreads();
            load_wt<32>(wt4, (const float4*)(W2 + l * 64 * 512), 64, 128, jt * 32, tid);
            __syncthreads();
            gemm_tile<2, 32, 64, false, true>(hts, wtf, ys, 64, 0,
                                              (jt == 0) ? (b2 + l * 64) : (const float*)nullptr,
                                              tx, ty);
            __syncthreads();
        }
        layernorm(ys, xs, ln2g + l * 64, ln2b + l * 64, tid);
        __syncthreads();
    }

    // ---- situation = LN(x[0] @ outW^T + outb) ----
    if (tid < 128) {
        float a = outb[tid];
        const float* wr = outW + tid * 64;
#pragma unroll
        for (int k = 0; k < 64; k++) a += xs[k] * wr[k];
        hts[tid] = a;
    }
    __syncthreads();
    if (tid < 128) {
        float v = hts[tid];
        float s = v, q = v * v;
#pragma unroll
        for (int off = 16; off; off >>= 1) {
            s += __shfl_xor_sync(0xffffffffu, s, off);
            q += __shfl_xor_sync(0xffffffffu, q, off);
        }
        if ((tid & 31) == 0) { red[tid >> 5] = s; red[4 + (tid >> 5)] = q; }
    }
    __syncthreads();
    if (tid < 128) {
        float S = red[0] + red[1] + red[2] + red[3];
        float Q = red[4] + red[5] + red[6] + red[7];
        float m = S * (1.f / 128.f);
        float var = Q * (1.f / 128.f) - m * m;
        float rs = rsqrtf(var + 1e-5f);
        out_sit[(size_t)b * 128 + tid] = (hts[tid] - m) * rs * outlng[tid] + outlnb[tid];
    }
    // ---- situation_sequence = x rows 1..24 ----
    for (int idx = tid; idx < STATE * DM; idx += TPB)
        out_seq[(size_t)b * STATE * DM + idx] = xs[DM + idx];
    // ---- new_memory = [memory_context rows 1..9, mean(seq rows)] ----
    for (int idx = tid; idx < 9 * DM; idx += TPB)
        out_mem[(size_t)b * MEMN * DM + idx] = memc[(size_t)b * MEMN * DM + DM + idx];
    if (tid < 64) {
        float s = 0.f;
#pragma unroll
        for (int i = 1; i <= STATE; i++) s += xs[i * 64 + tid];
        out_mem[(size_t)b * MEMN * DM + 9 * DM + tid] = s * (1.f / 24.f);
    }
}

extern "C" void kernel_launch(void* const* d_in, const int* in_sizes, int n_in,
                              void* d_out, int out_size) {
    const int*   toks     = (const int*)d_in[0];
    const float* traits   = (const float*)d_in[1];
    const float* rel      = (const float*)d_in[2];
    const float* memc     = (const float*)d_in[3];
    const float* temb     = (const float*)d_in[4];
    const float* demb     = (const float*)d_in[5];
    const float* trait_W  = (const float*)d_in[6];
    const float* trait_b  = (const float*)d_in[7];
    const float* intent_W = (const float*)d_in[8];
    const float* intent_b = (const float*)d_in[9];
    const float* cls      = (const float*)d_in[10];
    const float* Wqkv     = (const float*)d_in[11];
    const float* bqkv     = (const float*)d_in[12];
    const float* Wo       = (const float*)d_in[13];
    const float* bo       = (const float*)d_in[14];
    const float* ln1g     = (const float*)d_in[15];
    const float* ln1b     = (const float*)d_in[16];
    const float* W1       = (const float*)d_in[17];
    const float* b1       = (const float*)d_in[18];
    const float* W2       = (const float*)d_in[19];
    const float* b2       = (const float*)d_in[20];
    const float* outW     = (const float*)d_in[21 + 2];
    const float* outb     = (const float*)d_in[24];
    const float* outlng   = (const float*)d_in[25];
    const float* outlnb   = (const float*)d_in[26];
    const float* ln2g     = (const float*)d_in[21];
    const float* ln2b     = (const float*)d_in[22];

    int B = in_sizes[2] / STATE;  // rel_goal is (B, 24)
    float* out = (float*)d_out;
    float* out_sit = out;
    float* out_seq = out + (size_t)B * 128;
    float* out_mem = out_seq + (size_t)B * STATE * DM;

    base_kernel<<<STATE, DM>>>(toks, temb, demb, trait_b, intent_b);

    cudaFuncSetAttribute(fused_kernel, cudaFuncAttributeMaxDynamicSharedMemorySize, SMEM_BYTES);
    fused_kernel<<<B, TPB, SMEM_BYTES>>>(
        traits, rel, memc, trait_W, intent_W, cls,
        Wqkv, bqkv, Wo, bo, ln1g, ln1b, W1, b1, W2, b2, ln2g, ln2b,
        outW, outb, outlng, outlnb,
        out_sit, out_seq, out_mem);
}

// round 6
// speedup vs baseline: 1.1060x; 1.1060x over previous
#include <cuda_runtime.h>
#include <math.h>

#define TPB 256
#define NB 2
#define DM 64
#define STATE 24
#define MEMN 10
#define QSTR 193

typedef unsigned long long u64;

// smem float offsets (all multiples of 16)
#define WT_F   0            // 8192 floats (32KB) weight tile
#define XP_F   8192         // 5120 floats: paired x [40 pairs][64] u64
#define QKV_F  13312        // 15440 floats: qkv plain [80][193]
#define HTS_F  28752        // 10240 floats: paired hidden [40][128] u64 (also aop [40][64] u64)
#define YS_F   38992        // 5120 floats: plain x/residual [80][64]
#define RED_F  44112        // 16 floats
#define SMEM_FLOATS 44128
#define SMEM_BYTES (SMEM_FLOATS * 4)

static __device__ float g_base[STATE * DM];

__device__ __forceinline__ u64 ffma2(u64 a, u64 b, u64 c) {
    u64 r;
    asm("fma.rn.f32x2 %0, %1, %2, %3;" : "=l"(r) : "l"(a), "l"(b), "l"(c));
    return r;
}
__device__ __forceinline__ u64 dup2(float w) {
    unsigned u = __float_as_uint(w);
    u64 r;
    asm("mov.b64 %0, {%1, %2};" : "=l"(r) : "r"(u), "r"(u));
    return r;
}
__device__ __forceinline__ float2 unpk(u64 v) {
    unsigned a, b;
    asm("mov.b64 {%0, %1}, %2;" : "=r"(a), "=r"(b) : "l"(v));
    return make_float2(__uint_as_float(a), __uint_as_float(b));
}
__device__ __forceinline__ u64 pk(float x, float y) {
    unsigned a = __float_as_uint(x), b = __float_as_uint(y);
    u64 r;
    asm("mov.b64 %0, {%1, %2};" : "=l"(r) : "r"(a), "r"(b));
    return r;
}
__device__ __forceinline__ float gelu_f(float x) {
    return 0.5f * x * (1.0f + erff(x * 0.7071067811865475f));
}

template<int K4C>
__device__ __forceinline__ void load_wt(float4* wt, const float4* Wf4, int nrows,
                                        int rowStrideF4, int k4off, int tid) {
    int tot = nrows * K4C;
    for (int idx = tid; idx < tot; idx += TPB) {
        int n = idx / K4C;
        int k4 = idx - n * K4C;
        wt[k4 * nrows + n] = Wf4[n * rowStrideF4 + k4off + k4];
    }
}

// Row-pair-packed GEMM: acc[p][c] accumulates rows (2*(p0+p), 2*(p0+p)+1), col tx+32c.
// xp: paired A operand, xs u64 per pair-row. wt4: smem [k4][NT] float4.
template<int NC, int K4, int NT>
__device__ __forceinline__ void gemm_acc(const u64* __restrict__ xp, int xs,
                                         const float* __restrict__ wtf,
                                         u64 (&acc)[5][NC], int tx, int p0) {
    const float4* wt4 = reinterpret_cast<const float4*>(wtf);
#pragma unroll
    for (int k4 = 0; k4 < K4; k4++) {
        u64 wd[NC][4];
#pragma unroll
        for (int c = 0; c < NC; c++) {
            float4 w = wt4[k4 * NT + tx + 32 * c];
            wd[c][0] = dup2(w.x); wd[c][1] = dup2(w.y);
            wd[c][2] = dup2(w.z); wd[c][3] = dup2(w.w);
        }
#pragma unroll
        for (int p = 0; p < 5; p++) {
            const ulonglong2* xr = reinterpret_cast<const ulonglong2*>(xp + (p0 + p) * xs + k4 * 4);
            ulonglong2 a = xr[0], b = xr[1];  // broadcast
#pragma unroll
            for (int c = 0; c < NC; c++) {
                acc[p][c] = ffma2(a.x, wd[c][0], acc[p][c]);
                acc[p][c] = ffma2(a.y, wd[c][1], acc[p][c]);
                acc[p][c] = ffma2(b.x, wd[c][2], acc[p][c]);
                acc[p][c] = ffma2(b.y, wd[c][3], acc[p][c]);
            }
        }
    }
}

// LN rows of ys (plain, skip pad rows) -> ys (plain) and xp (paired halves)
__device__ __forceinline__ void layernorm(float* ys, float* xpf,
                                          const float* g, const float* b, int tid) {
    int w = tid >> 5, lane = tid & 31;
    float g0 = g[lane], g1 = g[lane + 32], b0 = b[lane], b1 = b[lane + 32];
    for (int row = w; row < 80; row += 8) {
        if ((row % 40) >= 35) continue;
        float v0 = ys[row * 64 + lane], v1 = ys[row * 64 + lane + 32];
        float s = v0 + v1, q = v0 * v0 + v1 * v1;
#pragma unroll
        for (int off = 16; off; off >>= 1) {
            s += __shfl_xor_sync(0xffffffffu, s, off);
            q += __shfl_xor_sync(0xffffffffu, q, off);
        }
        float m = s * (1.f / 64.f);
        float rs = rsqrtf(q * (1.f / 64.f) - m * m + 1e-5f);
        float o0 = (v0 - m) * rs * g0 + b0;
        float o1 = (v1 - m) * rs * g1 + b1;
        ys[row * 64 + lane] = o0;
        ys[row * 64 + lane + 32] = o1;
        int pr = row >> 1, hf = row & 1;
        xpf[(pr * 64 + lane) * 2 + hf] = o0;
        xpf[(pr * 64 + lane + 32) * 2 + hf] = o1;
    }
}

__global__ void base_kernel(const int* __restrict__ toks, const float* __restrict__ temb,
                            const float* __restrict__ demb, const float* __restrict__ trait_b,
                            const float* __restrict__ intent_b) {
    int i = blockIdx.x, d = threadIdx.x;
    float s = 0.f;
#pragma unroll
    for (int t = 0; t < 8; t++) s += temb[(size_t)toks[i * 8 + t] * DM + d];
    g_base[i * DM + d] = s * 0.125f + demb[i * DM + d] + trait_b[d] + intent_b[d];
}

__global__ void __launch_bounds__(TPB)
fused_kernel(const float* __restrict__ traits, const float* __restrict__ rel,
             const float* __restrict__ memc, const float* __restrict__ trait_W,
             const float* __restrict__ intent_W, const float* __restrict__ cls,
             const float* __restrict__ Wqkv, const float* __restrict__ bqkv,
             const float* __restrict__ Wo, const float* __restrict__ bo,
             const float* __restrict__ ln1g, const float* __restrict__ ln1b,
             const float* __restrict__ W1, const float* __restrict__ b1,
             const float* __restrict__ W2, const float* __restrict__ b2,
             const float* __restrict__ ln2g, const float* __restrict__ ln2b,
             const float* __restrict__ outW, const float* __restrict__ outb,
             const float* __restrict__ outlng, const float* __restrict__ outlnb,
             float* __restrict__ out_sit, float* __restrict__ out_seq,
             float* __restrict__ out_mem) {
    extern __shared__ float smem[];
    float* wtf = smem + WT_F;
    float4* wt4 = reinterpret_cast<float4*>(wtf);
    float* xpf = smem + XP_F;
    u64*   xpu = (u64*)xpf;
    float* qkv = smem + QKV_F;
    float* htf = smem + HTS_F;
    u64*   htu = (u64*)htf;
    float* ys  = smem + YS_F;
    float* red = smem + RED_F;

    const int tid = threadIdx.x;
    const int tx = tid & 31, ty = tid >> 5;
    const int p0 = ty * 5;
    const int gb0 = blockIdx.x * NB;

    // ---- build x: ys plain + xp paired (pad rows lr>=35 zero) ----
    for (int idx = tid; idx < 80 * DM; idx += TPB) {
        int row = idx >> 6, d = idx & 63;
        int b = row / 40, lr = row % 40, gb = gb0 + b;
        float v = 0.f;
        if (lr == 0) {
            v = cls[d];
        } else if (lr <= STATE) {
            int i = lr - 1;
            float t0 = traits[((size_t)gb * STATE + i) * 2];
            float t1 = traits[((size_t)gb * STATE + i) * 2 + 1];
            v = g_base[i * DM + d] + t0 * trait_W[d * 2] + t1 * trait_W[d * 2 + 1]
                + rel[(size_t)gb * STATE + i] * intent_W[d];
        } else if (lr < 35) {
            v = memc[((size_t)gb * MEMN + (lr - 25)) * DM + d];
        }
        ys[row * 64 + d] = v;
        xpf[((row >> 1) * 64 + d) * 2 + (row & 1)] = v;
    }
    __syncthreads();

    for (int l = 0; l < 3; l++) {
        // ======== QKV (two 96-wide halves) ========
        for (int hf = 0; hf < 2; hf++) {
            load_wt<16>(wt4, (const float4*)(Wqkv + (l * 192 + hf * 96) * 64), 96, 16, 0, tid);
            __syncthreads();
            u64 acc[5][3];
#pragma unroll
            for (int p = 0; p < 5; p++)
#pragma unroll
                for (int c = 0; c < 3; c++) acc[p][c] = 0ull;
            gemm_acc<3, 16, 96>(xpu, 64, wtf, acc, tx, p0);
#pragma unroll
            for (int p = 0; p < 5; p++)
#pragma unroll
                for (int c = 0; c < 3; c++) {
                    int n = hf * 96 + tx + 32 * c;
                    float2 v = unpk(acc[p][c]);
                    float bq = bqkv[l * 192 + n];
                    int r0 = 2 * (p0 + p);
                    qkv[r0 * QSTR + n] = v.x + bq;
                    qkv[(r0 + 1) * QSTR + n] = v.y + bq;
                }
            __syncthreads();
        }
        // ======== attention -> aop (paired, in HTS region) ========
        for (int t = tid; t < 560; t += TPB) {
            int i = t % 35, bh = t / 35, b = bh >> 3, h = bh & 7;
            int rb = b * 40;
            const float* qp = qkv + (rb + i) * QSTR + h * 8;
            float q[8];
#pragma unroll
            for (int d = 0; d < 8; d++) q[d] = qp[d];
            float sc[35];
            float mx = -1e30f;
#pragma unroll
            for (int j = 0; j < 35; j++) {
                const float* kp = qkv + (rb + j) * QSTR + 64 + h * 8;
                float a = 0.f;
#pragma unroll
                for (int d = 0; d < 8; d++) a += q[d] * kp[d];
                a *= 0.35355339059327373f;
                sc[j] = a;
                mx = fmaxf(mx, a);
            }
            float sum = 0.f;
#pragma unroll
            for (int j = 0; j < 35; j++) { float e = __expf(sc[j] - mx); sc[j] = e; sum += e; }
            float inv = 1.f / sum;
            int row = rb + i, pr = row >> 1, half = row & 1;
#pragma unroll
            for (int d = 0; d < 8; d++) {
                float o = 0.f;
#pragma unroll
                for (int j = 0; j < 35; j++) o += sc[j] * qkv[(rb + j) * QSTR + 128 + h * 8 + d];
                htf[(pr * 64 + h * 8 + d) * 2 + half] = o * inv;
            }
        }
        __syncthreads();
        // ======== Wo: ys += ao @ Wo^T + bo ; LN1 ========
        load_wt<16>(wt4, (const float4*)(Wo + l * 64 * 64), 64, 16, 0, tid);
        __syncthreads();
        {
            u64 acc[5][2];
#pragma unroll
            for (int p = 0; p < 5; p++) { acc[p][0] = 0ull; acc[p][1] = 0ull; }
            gemm_acc<2, 16, 64>(htu, 64, wtf, acc, tx, p0);
#pragma unroll
            for (int p = 0; p < 5; p++)
#pragma unroll
                for (int c = 0; c < 2; c++) {
                    int n = tx + 32 * c;
                    float2 v = unpk(acc[p][c]);
                    float bb = bo[l * 64 + n];
                    int r0 = 2 * (p0 + p);
                    ys[r0 * 64 + n] += v.x + bb;
                    ys[(r0 + 1) * 64 + n] += v.y + bb;
                }
        }
        __syncthreads();
        layernorm(ys, xpf, ln1g + l * 64, ln1b + l * 64, tid);
        __syncthreads();
        // ======== FF ========
        for (int jt = 0; jt < 4; jt++) {
            load_wt<16>(wt4, (const float4*)(W1 + (l * 512 + jt * 128) * 64), 128, 16, 0, tid);
            __syncthreads();
            {
                u64 acc[5][4];
#pragma unroll
                for (int p = 0; p < 5; p++)
#pragma unroll
                    for (int c = 0; c < 4; c++) acc[p][c] = 0ull;
                gemm_acc<4, 16, 128>(xpu, 64, wtf, acc, tx, p0);
#pragma unroll
                for (int p = 0; p < 5; p++)
#pragma unroll
                    for (int c = 0; c < 4; c++) {
                        int n = tx + 32 * c;
                        float2 v = unpk(acc[p][c]);
                        float bb = b1[l * 512 + jt * 128 + n];
                        htu[(p0 + p) * 128 + n] = pk(gelu_f(v.x + bb), gelu_f(v.y + bb));
                    }
            }
            __syncthreads();
            load_wt<32>(wt4, (const float4*)(W2 + l * 64 * 512), 64, 128, jt * 32, tid);
            __syncthreads();
            {
                u64 acc[5][2];
#pragma unroll
                for (int p = 0; p < 5; p++) { acc[p][0] = 0ull; acc[p][1] = 0ull; }
                gemm_acc<2, 32, 64>(htu, 128, wtf, acc, tx, p0);
#pragma unroll
                for (int p = 0; p < 5; p++)
#pragma unroll
                    for (int c = 0; c < 2; c++) {
                        int n = tx + 32 * c;
                        float2 v = unpk(acc[p][c]);
                        float bb = (jt == 0) ? b2[l * 64 + n] : 0.f;
                        int r0 = 2 * (p0 + p);
                        ys[r0 * 64 + n] += v.x + bb;
                        ys[(r0 + 1) * 64 + n] += v.y + bb;
                    }
            }
            __syncthreads();
        }
        layernorm(ys, xpf, ln2g + l * 64, ln2b + l * 64, tid);
        __syncthreads();
    }

    // ---- situation = LN(x[cls] @ outW^T + outb) for both batches ----
    {
        int bb = tid >> 7, j = tid & 127;
        int rb = bb * 40;
        float a = outb[j];
        const float* wr = outW + j * 64;
#pragma unroll
        for (int k = 0; k < 64; k++) a += ys[rb * 64 + k] * wr[k];
        qkv[bb * 128 + j] = a;  // reuse qkv as scratch
        float s = a, q = a * a;
#pragma unroll
        for (int off = 16; off; off >>= 1) {
            s += __shfl_xor_sync(0xffffffffu, s, off);
            q += __shfl_xor_sync(0xffffffffu, q, off);
        }
        if ((tid & 31) == 0) {
            red[bb * 8 + ((j >> 5) << 1)] = s;
            red[bb * 8 + ((j >> 5) << 1) + 1] = q;
        }
    }
    __syncthreads();
    {
        int bb = tid >> 7, j = tid & 127;
        float S = red[bb * 8] + red[bb * 8 + 2] + red[bb * 8 + 4] + red[bb * 8 + 6];
        float Q = red[bb * 8 + 1] + red[bb * 8 + 3] + red[bb * 8 + 5] + red[bb * 8 + 7];
        float m = S * (1.f / 128.f);
        float rs = rsqrtf(Q * (1.f / 128.f) - m * m + 1e-5f);
        out_sit[(size_t)(gb0 + bb) * 128 + j] =
            (qkv[bb * 128 + j] - m) * rs * outlng[j] + outlnb[j];
    }
    // ---- situation_sequence ----
    for (int idx = tid; idx < NB * STATE * DM; idx += TPB) {
        int b = idx / (STATE * DM), r = idx % (STATE * DM);
        out_seq[(size_t)(gb0 + b) * STATE * DM + r] = ys[(b * 40 + 1) * 64 + r];
    }
    // ---- new_memory ----
    for (int idx = tid; idx < NB * 9 * DM; idx += TPB) {
        int b = idx / (9 * DM), r = idx % (9 * DM);
        out_mem[(size_t)(gb0 + b) * MEMN * DM + r] = memc[(size_t)(gb0 + b) * MEMN * DM + DM + r];
    }
    if (tid < 128) {
        int bb = tid >> 6, d = tid & 63;
        float s = 0.f;
#pragma unroll
        for (int i = 1; i <= STATE; i++) s += ys[(bb * 40 + i) * 64 + d];
        out_mem[(size_t)(gb0 + bb) * MEMN * DM + 9 * DM + d] = s * (1.f / 24.f);
    }
}

extern "C" void kernel_launch(void* const* d_in, const int* in_sizes, int n_in,
                              void* d_out, int out_size) {
    const int*   toks     = (const int*)d_in[0];
    const float* traits   = (const float*)d_in[1];
    const float* rel      = (const float*)d_in[2];
    const float* memc     = (const float*)d_in[3];
    const float* temb     = (const float*)d_in[4];
    const float* demb     = (const float*)d_in[5];
    const float* trait_W  = (const float*)d_in[6];
    const float* trait_b  = (const float*)d_in[7];
    const float* intent_W = (const float*)d_in[8];
    const float* intent_b = (const float*)d_in[9];
    const float* cls      = (const float*)d_in[10];
    const float* Wqkv     = (const float*)d_in[11];
    const float* bqkv     = (const float*)d_in[12];
    const float* Wo       = (const float*)d_in[13];
    const float* bo       = (const float*)d_in[14];
    const float* ln1g     = (const float*)d_in[15];
    const float* ln1b     = (const float*)d_in[16];
    const float* W1       = (const float*)d_in[17];
    const float* b1       = (const float*)d_in[18];
    const float* W2       = (const float*)d_in[19];
    const float* b2       = (const float*)d_in[20];
    const float* ln2g     = (const float*)d_in[21];
    const float* ln2b     = (const float*)d_in[22];
    const float* outW     = (const float*)d_in[23];
    const float* outb     = (const float*)d_in[24];
    const float* outlng   = (const float*)d_in[25];
    const float* outlnb   = (const float*)d_in[26];

    int B = in_sizes[2] / STATE;
    float* out = (float*)d_out;
    float* out_sit = out;
    float* out_seq = out + (size_t)B * 128;
    float* out_mem = out_seq + (size_t)B * STATE * DM;

    base_kernel<<<STATE, DM>>>(toks, temb, demb, trait_b, intent_b);

    cudaFuncSetAttribute(fused_kernel, cudaFuncAttributeMaxDynamicSharedMemorySize, SMEM_BYTES);
    fused_kernel<<<B / NB, TPB, SMEM_BYTES>>>(
        traits, rel, memc, trait_W, intent_W, cls,
        Wqkv, bqkv, Wo, bo, ln1g, ln1b, W1, b1, W2, b2, ln2g, ln2b,
        outW, outb, outlng, outlnb,
        out_sit, out_seq, out_mem);
}

// round 9
// speedup vs baseline: 2.4055x; 2.1750x over previous
#include <cuda_runtime.h>
#include <cuda_bf16.h>
#include <math.h>
#include <stdint.h>

#define TPB 256
#define STATE 24
#define MEMN 10
#define NLAY 3

// smem float offsets
#define XH_F 0          // x-hi bf16 [80][64] swizzled (10KB)
#define XL_F 2560
#define BIG_F 5120      // qkv float [80][193] = 15440 floats; hidden h/l overlap
#define HH_F BIG_F
#define HL_F (BIG_F + 2560)
#define YS_F 20560      // [80][64]
#define SMEM_FLOATS 25684
#define SMEM_BYTES (SMEM_FLOATS * 4)

static __device__ float g_base[STATE * 64];
static __device__ uint4 g_qkvF[NLAY * 4 * 24 * 32];      // [l][kt][nt][lane]
static __device__ uint4 g_woF[NLAY * 4 * 8 * 32];
static __device__ uint4 g_w1F[NLAY * 8 * 4 * 8 * 32];    // [l][ct][kt][nt][lane]
static __device__ uint4 g_w2F[NLAY * 8 * 4 * 8 * 32];

__device__ __forceinline__ uint32_t smem_u32(const void* p) {
    uint32_t a;
    asm("{ .reg .u64 t; cvta.to.shared.u64 t, %1; cvt.u32.u64 %0, t; }" : "=r"(a) : "l"(p));
    return a;
}
__device__ __forceinline__ uint32_t pk2(float a, float b) {
    __nv_bfloat162 t = __floats2bfloat162_rn(a, b);
    return *reinterpret_cast<uint32_t*>(&t);
}
__device__ __forceinline__ void split2(float a, float b, uint32_t& h, uint32_t& l) {
    h = pk2(a, b);
    __nv_bfloat162 t = *reinterpret_cast<__nv_bfloat162*>(&h);
    l = pk2(a - __bfloat162float(t.x), b - __bfloat162float(t.y));
}
__device__ __forceinline__ int swb(int row, int col) {
    return row * 128 + (((col >> 3) ^ (row & 7)) << 4) + (col & 7) * 2;
}
__device__ __forceinline__ float gelu_f(float x) {
    return 0.5f * x * (1.0f + erff(x * 0.7071067811865475f));
}
__device__ __forceinline__ void mma_bf16(float* d, const uint32_t* a, uint32_t b0, uint32_t b1) {
    asm volatile(
        "mma.sync.aligned.m16n8k16.row.col.f32.bf16.bf16.f32 "
        "{%0,%1,%2,%3}, {%4,%5,%6,%7}, {%8,%9}, {%0,%1,%2,%3};"
        : "+f"(d[0]), "+f"(d[1]), "+f"(d[2]), "+f"(d[3])
        : "r"(a[0]), "r"(a[1]), "r"(a[2]), "r"(a[3]), "r"(b0), "r"(b1));
}
__device__ __forceinline__ void ldm4(uint32_t* r, uint32_t addr) {
    asm volatile("ldmatrix.sync.aligned.m8n8.x4.shared.b16 {%0,%1,%2,%3}, [%4];"
        : "=r"(r[0]), "=r"(r[1]), "=r"(r[2]), "=r"(r[3]) : "r"(addr));
}

// Warp GEMM: D[80][NT*8] += Xsplit @ Wsplit^T. A from swizzled smem bf16 (hi/lo),
// B frags preloaded in global (uint4 per [kt][ntglobal][lane]).
template<int NT>
__device__ __forceinline__ void gemm_w(uint32_t aH, uint32_t aL, const uint4* __restrict__ bf,
                                       int nt0, int ntot, float (&acc)[5][NT][4], int lane) {
    const uint32_t ab = (lane & 15) * 128;
    const int hi4 = lane >> 4, sw = lane & 7;
#pragma unroll
    for (int mt = 0; mt < 5; mt++) {
        uint32_t Ah[4][4], Al[4][4];
#pragma unroll
        for (int ks = 0; ks < 4; ks++) {
            uint32_t off = mt * 2048 + ab + (((2 * ks + hi4) ^ sw) << 4);
            ldm4(Ah[ks], aH + off);
            ldm4(Al[ks], aL + off);
        }
#pragma unroll
        for (int j = 0; j < NT; j++) {
#pragma unroll
            for (int ks = 0; ks < 4; ks++) {
                uint4 B = bf[(ks * ntot + nt0 + j) * 32 + lane];
                mma_bf16(acc[mt][j], Ah[ks], B.x, B.y);
                mma_bf16(acc[mt][j], Al[ks], B.x, B.y);
                mma_bf16(acc[mt][j], Ah[ks], B.z, B.w);
            }
        }
    }
}

__device__ __forceinline__ uint4 mkfrag(const float* W, int rs, int n, int k) {
    uint4 r;
    uint32_t h, l;
    split2(W[n * rs + k], W[n * rs + k + 1], h, l);
    r.x = h; r.z = l;
    split2(W[n * rs + k + 8], W[n * rs + k + 9], h, l);
    r.y = h; r.w = l;
    return r;
}

__global__ void base_kernel(const int* __restrict__ toks, const float* __restrict__ temb,
                            const float* __restrict__ demb, const float* __restrict__ trait_b,
                            const float* __restrict__ intent_b) {
    int i = blockIdx.x, d = threadIdx.x;
    float s = 0.f;
#pragma unroll
    for (int t = 0; t < 8; t++) s += temb[(size_t)toks[i * 8 + t] * 64 + d];
    g_base[i * 64 + d] = s * 0.125f + demb[i * 64 + d] + trait_b[d] + intent_b[d];
}

__global__ void prep_kernel(const float* __restrict__ Wqkv, const float* __restrict__ Wo,
                            const float* __restrict__ W1, const float* __restrict__ W2) {
    int st = gridDim.x * blockDim.x, t0 = blockIdx.x * blockDim.x + threadIdx.x;
    for (int i = t0; i < NLAY * 4 * 24 * 32; i += st) {
        int lane = i & 31, nt = (i >> 5) % 24, kt = (i >> 5) / 24 % 4, l = i / (32 * 24 * 4);
        g_qkvF[i] = mkfrag(Wqkv + l * 192 * 64, 64, nt * 8 + (lane >> 2), kt * 16 + (lane & 3) * 2);
    }
    for (int i = t0; i < NLAY * 4 * 8 * 32; i += st) {
        int lane = i & 31, nt = (i >> 5) % 8, kt = (i >> 5) / 8 % 4, l = i / (32 * 8 * 4);
        g_woF[i] = mkfrag(Wo + l * 64 * 64, 64, nt * 8 + (lane >> 2), kt * 16 + (lane & 3) * 2);
    }
    for (int i = t0; i < NLAY * 8 * 4 * 8 * 32; i += st) {
        int lane = i & 31, nt = (i >> 5) % 8, kt = (i >> 5) / 8 % 4;
        int ct = (i >> 5) / 32 % 8, l = i / (32 * 8 * 4 * 8);
        g_w1F[i] = mkfrag(W1 + l * 512 * 64, 64, ct * 64 + nt * 8 + (lane >> 2),
                          kt * 16 + (lane & 3) * 2);
    }
    for (int i = t0; i < NLAY * 8 * 4 * 8 * 32; i += st) {
        int lane = i & 31, nt = (i >> 5) % 8, kt = (i >> 5) / 8 % 4;
        int ct = (i >> 5) / 32 % 8, l = i / (32 * 8 * 4 * 8);
        g_w2F[i] = mkfrag(W2 + l * 64 * 512, 512, nt * 8 + (lane >> 2),
                          ct * 64 + kt * 16 + (lane & 3) * 2);
    }
}

__device__ __forceinline__ void ln_pass(float* ys, char* xhB, char* xlB,
                                        const float* g, const float* bb, int tid) {
    int w = tid >> 5, lane = tid & 31;
    for (int row = w; row < 80; row += 8) {
        float2 v = ((float2*)ys)[row * 32 + lane];
        float s = v.x + v.y, q = v.x * v.x + v.y * v.y;
#pragma unroll
        for (int off = 16; off; off >>= 1) {
            s += __shfl_xor_sync(0xffffffffu, s, off);
            q += __shfl_xor_sync(0xffffffffu, q, off);
        }
        float mn = s * (1.f / 64.f);
        float rs = rsqrtf(q * (1.f / 64.f) - mn * mn + 1e-5f);
        bool real = (row % 40) < 35;
        float o0 = real ? (v.x - mn) * rs * g[lane * 2] + bb[lane * 2] : 0.f;
        float o1 = real ? (v.y - mn) * rs * g[lane * 2 + 1] + bb[lane * 2 + 1] : 0.f;
        ((float2*)ys)[row * 32 + lane] = make_float2(o0, o1);
        uint32_t h, l2;
        split2(o0, o1, h, l2);
        int byte = swb(row, lane * 2);
        *(uint32_t*)(xhB + byte) = h;
        *(uint32_t*)(xlB + byte) = l2;
    }
}

__global__ void __launch_bounds__(TPB, 2)
fused_kernel(const float* __restrict__ traits, const float* __restrict__ rel,
             const float* __restrict__ memc, const float* __restrict__ trait_W,
             const float* __restrict__ intent_W, const float* __restrict__ cls,
             const float* __restrict__ bqkv, const float* __restrict__ bo,
             const float* __restrict__ ln1g, const float* __restrict__ ln1b,
             const float* __restrict__ b1, const float* __restrict__ b2,
             const float* __restrict__ ln2g, const float* __restrict__ ln2b,
             const float* __restrict__ outW, const float* __restrict__ outb,
             const float* __restrict__ outlng, const float* __restrict__ outlnb,
             float* __restrict__ out_sit, float* __restrict__ out_seq,
             float* __restrict__ out_mem) {
    extern __shared__ float smem[];
    char* xhB = (char*)(smem + XH_F);
    char* xlB = (char*)(smem + XL_F);
    char* hhB = (char*)(smem + HH_F);
    char* hlB = (char*)(smem + HL_F);
    float* qkv = smem + BIG_F;
    float* ys  = smem + YS_F;

    const int tid = threadIdx.x;
    const int wid = tid >> 5, lane = tid & 31;
    const uint32_t sb = smem_u32(smem);
    const uint32_t xh_a = sb + XH_F * 4, xl_a = sb + XL_F * 4;
    const uint32_t hh_a = sb + HH_F * 4, hl_a = sb + HL_F * 4;
    const int gb0 = blockIdx.x * 2;
    const int r0l = lane >> 2, ql = lane & 3;

    // ---- build x: ys float + xh/xl swizzled bf16 ----
    for (int idx = tid; idx < 80 * 32; idx += TPB) {
        int row = idx >> 5, cp = idx & 31;
        int slot = row / 40, lr = row % 40, gb = gb0 + slot;
        float v[2];
#pragma unroll
        for (int u = 0; u < 2; u++) {
            int d = cp * 2 + u;
            float x = 0.f;
            if (lr == 0) x = cls[d];
            else if (lr <= STATE) {
                int i = lr - 1;
                x = g_base[i * 64 + d]
                    + traits[((size_t)gb * STATE + i) * 2] * trait_W[d * 2]
                    + traits[((size_t)gb * STATE + i) * 2 + 1] * trait_W[d * 2 + 1]
                    + rel[(size_t)gb * STATE + i] * intent_W[d];
            } else if (lr < 35) {
                x = memc[((size_t)gb * MEMN + (lr - 25)) * 64 + d];
            }
            v[u] = x;
        }
        ((float2*)ys)[row * 32 + cp] = make_float2(v[0], v[1]);
        uint32_t h, l;
        split2(v[0], v[1], h, l);
        int byte = swb(row, cp * 2);
        *(uint32_t*)(xhB + byte) = h;
        *(uint32_t*)(xlB + byte) = l;
    }
    __syncthreads();

    for (int l = 0; l < NLAY; l++) {
        // ======== QKV: each warp covers 24 cols ========
        {
            float acc[5][3][4];
#pragma unroll
            for (int m = 0; m < 5; m++)
#pragma unroll
                for (int j = 0; j < 3; j++)
#pragma unroll
                    for (int c = 0; c < 4; c++) acc[m][j][c] = 0.f;
            gemm_w<3>(xh_a, xl_a, g_qkvF + l * 4 * 24 * 32, wid * 3, 24, acc, lane);
#pragma unroll
            for (int m = 0; m < 5; m++)
#pragma unroll
                for (int j = 0; j < 3; j++) {
                    int row = m * 16 + r0l;
                    int n = (wid * 3 + j) * 8 + ql * 2;
                    float bb0 = bqkv[l * 192 + n], bb1 = bqkv[l * 192 + n + 1];
                    qkv[row * 193 + n] = acc[m][j][0] + bb0;
                    qkv[row * 193 + n + 1] = acc[m][j][1] + bb1;
                    qkv[(row + 8) * 193 + n] = acc[m][j][2] + bb0;
                    qkv[(row + 8) * 193 + n + 1] = acc[m][j][3] + bb1;
                }
        }
        __syncthreads();
        // ======== attention -> xh/xl ========
        for (int t = tid; t < 560; t += TPB) {
            int i = t % 35, sh = t / 35, slot = sh >> 3, h = sh & 7;
            int rb = slot * 40;
            float q[8];
#pragma unroll
            for (int d = 0; d < 8; d++) q[d] = qkv[(rb + i) * 193 + h * 8 + d];
            float sc[35];
            float mx = -1e30f;
#pragma unroll
            for (int j = 0; j < 35; j++) {
                const float* kp = qkv + (rb + j) * 193 + 64 + h * 8;
                float a = 0.f;
#pragma unroll
                for (int d = 0; d < 8; d++) a += q[d] * kp[d];
                a *= 0.35355339059327373f;
                sc[j] = a;
                mx = fmaxf(mx, a);
            }
            float sum = 0.f;
#pragma unroll
            for (int j = 0; j < 35; j++) { float e = __expf(sc[j] - mx); sc[j] = e; sum += e; }
            float inv = 1.f / sum;
            float o[8];
#pragma unroll
            for (int d = 0; d < 8; d++) {
                float acc = 0.f;
#pragma unroll
                for (int j = 0; j < 35; j++) acc += sc[j] * qkv[(rb + j) * 193 + 128 + h * 8 + d];
                o[d] = acc * inv;
            }
            int row = rb + i;
#pragma unroll
            for (int d = 0; d < 8; d += 2) {
                uint32_t hh, ll;
                split2(o[d], o[d + 1], hh, ll);
                int byte = swb(row, h * 8 + d);
                *(uint32_t*)(xhB + byte) = hh;
                *(uint32_t*)(xlB + byte) = ll;
            }
        }
        __syncthreads();
        // ======== Wo ========
        {
            float acc[5][1][4];
#pragma unroll
            for (int m = 0; m < 5; m++)
#pragma unroll
                for (int c = 0; c < 4; c++) acc[m][0][c] = 0.f;
            gemm_w<1>(xh_a, xl_a, g_woF + l * 4 * 8 * 32, wid, 8, acc, lane);
#pragma unroll
            for (int m = 0; m < 5; m++) {
                int row = m * 16 + r0l;
                int n = wid * 8 + ql * 2;
                float bb0 = bo[l * 64 + n], bb1 = bo[l * 64 + n + 1];
                ys[row * 64 + n] += acc[m][0][0] + bb0;
                ys[row * 64 + n + 1] += acc[m][0][1] + bb1;
                ys[(row + 8) * 64 + n] += acc[m][0][2] + bb0;
                ys[(row + 8) * 64 + n + 1] += acc[m][0][3] + bb1;
            }
        }
        __syncthreads();
        ln_pass(ys, xhB, xlB, ln1g + l * 64, ln1b + l * 64, tid);
        __syncthreads();
        // ======== FF (8 chunks of 64) ========
        {
            float acc2[5][1][4];
#pragma unroll
            for (int m = 0; m < 5; m++)
#pragma unroll
                for (int c = 0; c < 4; c++) acc2[m][0][c] = 0.f;
            for (int ct = 0; ct < 8; ct++) {
                float acc1[5][1][4];
#pragma unroll
                for (int m = 0; m < 5; m++)
#pragma unroll
                    for (int c = 0; c < 4; c++) acc1[m][0][c] = 0.f;
                gemm_w<1>(xh_a, xl_a, g_w1F + (l * 8 + ct) * 4 * 8 * 32, wid, 8, acc1, lane);
#pragma unroll
                for (int m = 0; m < 5; m++) {
                    int row = m * 16 + r0l;
                    int n = wid * 8 + ql * 2;
                    float bb0 = b1[l * 512 + ct * 64 + n], bb1 = b1[l * 512 + ct * 64 + n + 1];
                    uint32_t h, lo2;
                    split2(gelu_f(acc1[m][0][0] + bb0), gelu_f(acc1[m][0][1] + bb1), h, lo2);
                    int byte = swb(row, n);
                    *(uint32_t*)(hhB + byte) = h;
                    *(uint32_t*)(hlB + byte) = lo2;
                    split2(gelu_f(acc1[m][0][2] + bb0), gelu_f(acc1[m][0][3] + bb1), h, lo2);
                    byte = swb(row + 8, n);
                    *(uint32_t*)(hhB + byte) = h;
                    *(uint32_t*)(hlB + byte) = lo2;
                }
                __syncthreads();
                gemm_w<1>(hh_a, hl_a, g_w2F + (l * 8 + ct) * 4 * 8 * 32, wid, 8, acc2, lane);
                __syncthreads();
            }
#pragma unroll
            for (int m = 0; m < 5; m++) {
                int row = m * 16 + r0l;
                int n = wid * 8 + ql * 2;
                float bb0 = b2[l * 64 + n], bb1 = b2[l * 64 + n + 1];
                ys[row * 64 + n] += acc2[m][0][0] + bb0;
                ys[row * 64 + n + 1] += acc2[m][0][1] + bb1;
                ys[(row + 8) * 64 + n] += acc2[m][0][2] + bb0;
                ys[(row + 8) * 64 + n + 1] += acc2[m][0][3] + bb1;
            }
        }
        __syncthreads();
        ln_pass(ys, xhB, xlB, ln2g + l * 64, ln2b + l * 64, tid);
        __syncthreads();
    }

    // ---- head: situation = LN128(x[cls] @ outW^T + outb) ----
    {
        int slot = tid >> 7, j = tid & 127;
        float a = outb[j];
        const float* wr = outW + j * 64;
        const float* xr = ys + (slot * 40) * 64;
#pragma unroll
        for (int k = 0; k < 64; k++) a += xr[k] * wr[k];
        qkv[slot * 128 + j] = a;
    }
    __syncthreads();
    if (wid < 2) {
        float v4[4];
        float s = 0.f, q = 0.f;
#pragma unroll
        for (int u = 0; u < 4; u++) {
            float v = qkv[wid * 128 + lane * 4 + u];
            v4[u] = v; s += v; q += v * v;
        }
#pragma unroll
        for (int off = 16; off; off >>= 1) {
            s += __shfl_xor_sync(0xffffffffu, s, off);
            q += __shfl_xor_sync(0xffffffffu, q, off);
        }
        float mn = s * (1.f / 128.f);
        float rs = rsqrtf(q * (1.f / 128.f) - mn * mn + 1e-5f);
#pragma unroll
        for (int u = 0; u < 4; u++) {
            int j = lane * 4 + u;
            out_sit[(size_t)(gb0 + wid) * 128 + j] = (v4[u] - mn) * rs * outlng[j] + outlnb[j];
        }
    }
    for (int idx = tid; idx < 2 * STATE * 64; idx += TPB) {
        int slot = idx / (STATE * 64), r2 = idx % (STATE * 64);
        out_seq[(size_t)(gb0 + slot) * STATE * 64 + r2] =
            ys[(slot * 40 + 1 + (r2 >> 6)) * 64 + (r2 & 63)];
    }
    for (int idx = tid; idx < 2 * 9 * 64; idx += TPB) {
        int slot = idx / (9 * 64), r2 = idx % (9 * 64);
        out_mem[(size_t)(gb0 + slot) * 640 + r2] = memc[(size_t)(gb0 + slot) * 640 + 64 + r2];
    }
    if (tid < 128) {
        int slot = tid >> 6, d = tid & 63;
        float s = 0.f;
#pragma unroll
        for (int i = 1; i <= STATE; i++) s += ys[(slot * 40 + i) * 64 + d];
        out_mem[(size_t)(gb0 + slot) * 640 + 9 * 64 + d] = s * (1.f / 24.f);
    }
}

extern "C" void kernel_launch(void* const* d_in, const int* in_sizes, int n_in,
                              void* d_out, int out_size) {
    const int*   toks     = (const int*)d_in[0];
    const float* traits   = (const float*)d_in[1];
    const float* rel      = (const float*)d_in[2];
    const float* memc     = (const float*)d_in[3];
    const float* temb     = (const float*)d_in[4];
    const float* demb     = (const float*)d_in[5];
    const float* trait_W  = (const float*)d_in[6];
    const float* trait_b  = (const float*)d_in[7];
    const float* intent_W = (const float*)d_in[8];
    const float* intent_b = (const float*)d_in[9];
    const float* cls      = (const float*)d_in[10];
    const float* Wqkv     = (const float*)d_in[11];
    const float* bqkv     = (const float*)d_in[12];
    const float* Wo       = (const float*)d_in[13];
    const float* bo       = (const float*)d_in[14];
    const float* ln1g     = (const float*)d_in[15];
    const float* ln1b     = (const float*)d_in[16];
    const float* W1       = (const float*)d_in[17];
    const float* b1       = (const float*)d_in[18];
    const float* W2       = (const float*)d_in[19];
    const float* b2       = (const float*)d_in[20];
    const float* ln2g     = (const float*)d_in[21];
    const float* ln2b     = (const float*)d_in[22];
    const float* outW     = (const float*)d_in[23];
    const float* outb     = (const float*)d_in[24];
    const float* outlng   = (const float*)d_in[25];
    const float* outlnb   = (const float*)d_in[26];

    int B = in_sizes[2] / STATE;
    float* out = (float*)d_out;
    float* out_sit = out;
    float* out_seq = out + (size_t)B * 128;
    float* out_mem = out_seq + (size_t)B * STATE * 64;

    base_kernel<<<STATE, 64>>>(toks, temb, demb, trait_b, intent_b);
    prep_kernel<<<120, 256>>>(Wqkv, Wo, W1, W2);

    cudaFuncSetAttribute(fused_kernel, cudaFuncAttributeMaxDynamicSharedMemorySize, SMEM_BYTES);
    fused_kernel<<<B / 2, TPB, SMEM_BYTES>>>(
        traits, rel, memc, trait_W, intent_W, cls,
        bqkv, bo, ln1g, ln1b, b1, b2, ln2g, ln2b,
        outW, outb, outlng, outlnb,
        out_sit, out_seq, out_mem);
}